// round 8
// baseline (speedup 1.0000x reference)
#include <cuda_runtime.h>
#include <cuda_fp16.h>
#include <cstdint>

// ---------------- problem constants ----------------
#define HW    112
#define IMG   (HW*HW)          // 12544
#define NB    32
#define CIN   128
#define COUT  256
#define NPOS  (NB*IMG)         // 401408
#define KTOT  1152             // 3*3*128

// ---------------- scratch ( __device__ globals ) ----------------
__device__ __half g_xq[(size_t)NPOS * CIN];           // fp16 copy of x
__device__ __half g_wbin[(size_t)COUT * KTOT];        // sign(w) fp16, [co][tap*128+c]

// ---------------- helpers (sm_80-level base ISA) ----------------
__device__ __forceinline__ uint32_t smem_to_u32(const void* p) {
    uint32_t a;
    asm("{ .reg .u64 t; cvta.to.shared.u64 t, %1; cvt.u32.u64 %0, t; }" : "=r"(a) : "l"(p));
    return a;
}

__device__ __forceinline__ void cp16(uint32_t dst, const void* src, bool pred) {
    int sz = pred ? 16 : 0;     // src-size 0 -> 16B zfill
    asm volatile("cp.async.cg.shared.global [%0], [%1], 16, %2;"
                 :: "r"(dst), "l"(src), "r"(sz) : "memory");
}

#define CP_COMMIT() asm volatile("cp.async.commit_group;" ::: "memory")
#define CP_WAIT2()  asm volatile("cp.async.wait_group 2;" ::: "memory")

__device__ __forceinline__ void ldsm4(uint32_t* r, uint32_t addr) {
    asm volatile("ldmatrix.sync.aligned.m8n8.x4.shared.b16 {%0,%1,%2,%3}, [%4];"
                 : "=r"(r[0]), "=r"(r[1]), "=r"(r[2]), "=r"(r[3]) : "r"(addr));
}

__device__ __forceinline__ void mma_f16(float* c, const uint32_t* a,
                                        uint32_t b0, uint32_t b1) {
    asm volatile(
        "mma.sync.aligned.m16n8k16.row.col.f32.f16.f16.f32 "
        "{%0,%1,%2,%3}, {%4,%5,%6,%7}, {%8,%9}, {%0,%1,%2,%3};"
        : "+f"(c[0]), "+f"(c[1]), "+f"(c[2]), "+f"(c[3])
        : "r"(a[0]), "r"(a[1]), "r"(a[2]), "r"(a[3]), "r"(b0), "r"(b1));
}

// ---------------- SMEM layout ----------------
// 4 stages. stage s at s*49152: A0 16KB | A1 16KB | B 16KB
// rows = 128 bytes (64 fp16), XOR swizzle on 16B units (u ^ (row&7))
static constexpr int BUF_BYTES = 49152;
static constexpr int A_SUB     = 16384;
static constexpr int B_OFF     = 32768;
static constexpr int DYN_SMEM  = 4 * BUF_BYTES;   // 196608

// ---------------- prep kernels ----------------
__global__ void binarize_kernel(const float* __restrict__ w) {
    int i = blockIdx.x * blockDim.x + threadIdx.x;
    if (i >= COUT * KTOT) return;
    int k  = i >> 8;          // HWIO: co fastest
    int co = i & 255;
    float v = w[i];
    float s = (v > 0.f) ? 1.f : ((v < 0.f) ? -1.f : 0.f);
    g_wbin[co * KTOT + k] = __float2half_rn(s);
}

__global__ void quant_kernel(const float4* __restrict__ x) {
    int i = blockIdx.x * blockDim.x + threadIdx.x;
    if (i >= (NPOS * CIN) / 4) return;
    float4 v = x[i];
    __half2 p0 = make_half2(__float2half_rn(v.x), __float2half_rn(v.y));
    __half2 p1 = make_half2(__float2half_rn(v.z), __float2half_rn(v.w));
    uint2 pk;
    pk.x = *(uint32_t*)&p0;
    pk.y = *(uint32_t*)&p1;
    ((uint2*)g_xq)[i] = pk;
}

// ---------------- main implicit-GEMM conv (fp16 HMMA) ----------------
// Launched twice (nt = 0,1). CTA tile M=256 x N=128. 8 warps, warp tile 64x64.
// 18 K-chunks (9 taps x 2 ch-halves), chunk = K=64 fp16. 4-stage cp.async,
// one __syncthreads per chunk, ks-level fragment double buffering.
__global__ __launch_bounds__(256, 1)
void conv_kernel(float* __restrict__ out, int nt) {
    extern __shared__ char smem[];
    const uint32_t smem_u = smem_to_u32(smem);
    const int tid  = threadIdx.x;
    const int wid  = tid >> 5;
    const int lane = tid & 31;
    const int mt   = blockIdx.x;

    // ---- per-thread load slots (fixed across the K loop) ----
    // A: 8 slots (2048 uint4 / 256 thr)
    int cbase[8], hh[8], ww[8];
    uint32_t dstA[8];
#pragma unroll
    for (int j = 0; j < 8; ++j) {
        int s = tid + j * 256;
        int t = s >> 10;            // M subtile 0/1
        int r = (s >> 3) & 127;     // row in subtile
        int u = s & 7;              // 16B unit
        int p = mt * 256 + t * 128 + r;
        int n = p / IMG;
        int rem = p - n * IMG;
        int h = rem / HW;
        int w = rem - h * HW;
        hh[j] = h; ww[j] = w;
        cbase[j] = ((n * HW + h) * HW + w) * CIN + u * 8;    // in halfs
        dstA[j]  = t * A_SUB + r * 128 + ((u ^ (r & 7)) << 4);
    }
    // B: 4 slots (1024 uint4 / 256 thr)
    int bsrc[4];
    uint32_t dstB[4];
#pragma unroll
    for (int j = 0; j < 4; ++j) {
        int s = tid + j * 256;
        int r = s >> 3;
        int u = s & 7;
        bsrc[j] = (nt * 128 + r) * KTOT + u * 8;             // in halfs
        dstB[j] = B_OFF + r * 128 + ((u ^ (r & 7)) << 4);
    }

    // ---- warp tiling: 4 warps in M x 2 warps in N ----
    const int wm = (wid & 3) * 64;      // 0..192
    const int wn = (wid >> 2) * 64;     // 0 or 64
    const int at = wm >> 7;
    const int am = wm & 127;

    float acc[4][8][4];
#pragma unroll
    for (int i = 0; i < 4; ++i)
#pragma unroll
        for (int j = 0; j < 8; ++j)
#pragma unroll
            for (int q = 0; q < 4; ++q) acc[i][j][q] = 0.f;

    auto issue_loads = [&](int it, int buf) {
        int tap = it >> 1;
        int chh = it & 1;
        int kh = tap / 3, kw = tap - kh * 3;
        const int doff = ((kh - 1) * HW + (kw - 1)) * CIN + chh * 64;  // halfs
        const uint32_t bb = smem_u + buf * BUF_BYTES;
#pragma unroll
        for (int j = 0; j < 8; ++j) {
            unsigned h2 = (unsigned)(hh[j] + kh - 1);
            unsigned w2 = (unsigned)(ww[j] + kw - 1);
            bool ok = (h2 < (unsigned)HW) && (w2 < (unsigned)HW);
            cp16(bb + dstA[j], g_xq + cbase[j] + doff, ok);
        }
        const int woff = tap * CIN + chh * 64;                          // halfs
#pragma unroll
        for (int j = 0; j < 4; ++j)
            cp16(bb + dstB[j], g_wbin + bsrc[j] + woff, true);
    };

    issue_loads(0, 0); CP_COMMIT();
    issue_loads(1, 1); CP_COMMIT();
    issue_loads(2, 2); CP_COMMIT();

    const int arow = am + (lane & 15);
    const int brow = wn + (lane & 15);
    const int khi  = (lane >> 4) << 4;   // byte half select

    for (int it = 0; it < 18; ++it) {
        CP_WAIT2();                 // chunk `it` resident
        __syncthreads();            // all warps past chunk it-1; its buffer free
        if (it + 3 < 18) issue_loads(it + 3, (it + 3) & 3);
        CP_COMMIT();

        const uint32_t bb    = smem_u + (it & 3) * BUF_BYTES;
        const uint32_t Abase = bb + at * A_SUB;
        const uint32_t Bbase = bb + B_OFF;

        uint32_t a[2][4][4];        // [pingpong][mf][frag]
        uint32_t b[2][4][4];        // [pingpong][q ][frag]

        auto load_frags = [&](int ks, int pb) {
            const int kb = ks * 32 + khi;
#pragma unroll
            for (int mf = 0; mf < 4; ++mf) {
                int row = arow + mf * 16;
                uint32_t off = (uint32_t)(row * 128 + kb) ^ (uint32_t)((row & 7) << 4);
                ldsm4(a[pb][mf], Abase + off);
            }
#pragma unroll
            for (int q = 0; q < 4; ++q) {
                int row = brow + q * 16;
                uint32_t off = (uint32_t)(row * 128 + kb) ^ (uint32_t)((row & 7) << 4);
                ldsm4(b[pb][q], Bbase + off);
            }
        };

        load_frags(0, 0);
#pragma unroll
        for (int ks = 0; ks < 4; ++ks) {
            const int cur = ks & 1;
            if (ks < 3) load_frags(ks + 1, cur ^ 1);
#pragma unroll
            for (int mf = 0; mf < 4; ++mf)
#pragma unroll
                for (int nb = 0; nb < 8; ++nb) {
                    int q = nb >> 1, jj = nb & 1;
                    mma_f16(acc[mf][nb], a[cur][mf], b[cur][q][jj], b[cur][q][jj + 2]);
                }
        }
    }

    // ---- epilogue: registers -> gmem ----
    const int r0 = lane >> 2;
    const int c0 = (lane & 3) * 2;
#pragma unroll
    for (int mf = 0; mf < 4; ++mf) {
        int m = mt * 256 + wm + mf * 16 + r0;
#pragma unroll
        for (int nb = 0; nb < 8; ++nb) {
            int co = nt * 128 + wn + nb * 8 + c0;
            float* p0 = out + (size_t)m * COUT + co;
            float* p1 = out + (size_t)(m + 8) * COUT + co;
            *(float2*)p0 = make_float2(acc[mf][nb][0], acc[mf][nb][1]);
            *(float2*)p1 = make_float2(acc[mf][nb][2], acc[mf][nb][3]);
        }
    }
}

// ---------------- launch ----------------
extern "C" void kernel_launch(void* const* d_in, const int* in_sizes, int n_in,
                              void* d_out, int out_size) {
    const float* x = (const float*)d_in[0];
    const float* w = (const float*)d_in[1];
    float* out = (float*)d_out;

    cudaFuncSetAttribute(conv_kernel,
                         cudaFuncAttributeMaxDynamicSharedMemorySize, DYN_SMEM);

    binarize_kernel<<<(COUT * KTOT + 255) / 256, 256>>>(w);
    quant_kernel<<<(NPOS * CIN / 4 + 255) / 256, 256>>>((const float4*)x);
    conv_kernel<<<NPOS / 256, 256, DYN_SMEM>>>(out, 0);
    conv_kernel<<<NPOS / 256, 256, DYN_SMEM>>>(out, 1);
}

// round 9
// speedup vs baseline: 1.0579x; 1.0579x over previous
#include <cuda_runtime.h>
#include <cuda_fp16.h>
#include <cstdint>

// ---------------- problem constants ----------------
#define HW    112
#define IMG   (HW*HW)          // 12544
#define NB    32
#define CIN   128
#define COUT  256
#define NPOS  (NB*IMG)         // 401408
#define KTOT  1152             // 3*3*128

// ---------------- scratch ( __device__ globals ) ----------------
__device__ __half g_xq[(size_t)NPOS * CIN];           // fp16 copy of x
__device__ __half g_wbin[(size_t)COUT * KTOT];        // sign(w) fp16, [co][tap*128+c]

// ---------------- helpers (sm_80-level base ISA) ----------------
__device__ __forceinline__ uint32_t smem_to_u32(const void* p) {
    uint32_t a;
    asm("{ .reg .u64 t; cvta.to.shared.u64 t, %1; cvt.u32.u64 %0, t; }" : "=r"(a) : "l"(p));
    return a;
}

__device__ __forceinline__ void cp16(uint32_t dst, const void* src, bool pred) {
    int sz = pred ? 16 : 0;     // src-size 0 -> 16B zfill
    asm volatile("cp.async.cg.shared.global [%0], [%1], 16, %2;"
                 :: "r"(dst), "l"(src), "r"(sz) : "memory");
}

#define CP_COMMIT() asm volatile("cp.async.commit_group;" ::: "memory")
#define CP_WAIT1()  asm volatile("cp.async.wait_group 1;" ::: "memory")

__device__ __forceinline__ void ldsm4(uint32_t* r, uint32_t addr) {
    asm volatile("ldmatrix.sync.aligned.m8n8.x4.shared.b16 {%0,%1,%2,%3}, [%4];"
                 : "=r"(r[0]), "=r"(r[1]), "=r"(r[2]), "=r"(r[3]) : "r"(addr));
}

__device__ __forceinline__ void mma_f16(float* c, const uint32_t* a,
                                        uint32_t b0, uint32_t b1) {
    asm volatile(
        "mma.sync.aligned.m16n8k16.row.col.f32.f16.f16.f32 "
        "{%0,%1,%2,%3}, {%4,%5,%6,%7}, {%8,%9}, {%0,%1,%2,%3};"
        : "+f"(c[0]), "+f"(c[1]), "+f"(c[2]), "+f"(c[3])
        : "r"(a[0]), "r"(a[1]), "r"(a[2]), "r"(a[3]), "r"(b0), "r"(b1));
}

// ---------------- SMEM layout ----------------
// 3 stages. stage s at s*32768: A 16KB | B 16KB
// rows = 128 bytes (64 fp16), XOR swizzle on 16B units (u ^ (row&7))
static constexpr int BUF_BYTES = 32768;
static constexpr int B_OFF     = 16384;
static constexpr int DYN_SMEM  = 3 * BUF_BYTES;   // 98304 per CTA -> 2 CTAs/SM

// ---------------- prep kernels ----------------
__global__ void binarize_kernel(const float* __restrict__ w) {
    int i = blockIdx.x * blockDim.x + threadIdx.x;
    if (i >= COUT * KTOT) return;
    int k  = i >> 8;          // HWIO: co fastest
    int co = i & 255;
    float v = w[i];
    float s = (v > 0.f) ? 1.f : ((v < 0.f) ? -1.f : 0.f);
    g_wbin[co * KTOT + k] = __float2half_rn(s);
}

__global__ void quant_kernel(const float4* __restrict__ x) {
    int i = blockIdx.x * blockDim.x + threadIdx.x;
    if (i >= (NPOS * CIN) / 4) return;
    float4 v = x[i];
    __half2 p0 = make_half2(__float2half_rn(v.x), __float2half_rn(v.y));
    __half2 p1 = make_half2(__float2half_rn(v.z), __float2half_rn(v.w));
    uint2 pk;
    pk.x = *(uint32_t*)&p0;
    pk.y = *(uint32_t*)&p1;
    ((uint2*)g_xq)[i] = pk;
}

// ---------------- main implicit-GEMM conv (fp16 HMMA) ----------------
// Launched twice (nt = 0,1). CTA tile M=128 x N=128, 256 threads, 2 CTAs/SM.
// 8 warps, warp tile 64x32 (2 M-warps x 4 N-warps). 18 K-chunks (9 taps x 2
// channel-halves), chunk = K=64 fp16. 3-stage cp.async pipeline.
__global__ __launch_bounds__(256, 2)
void conv_kernel(float* __restrict__ out, int nt) {
    extern __shared__ char smem[];
    const uint32_t smem_u = smem_to_u32(smem);
    const int tid  = threadIdx.x;
    const int wid  = tid >> 5;
    const int lane = tid & 31;
    const int mt   = blockIdx.x;

    // ---- per-thread load slots (fixed across the K loop) ----
    // A: 4 slots (128 rows x 8 x 16B = 1024 uint4 / 256 thr)
    int cbase[4], hh[4], ww[4];
    uint32_t dstA[4];
#pragma unroll
    for (int j = 0; j < 4; ++j) {
        int s = tid + j * 256;
        int r = s >> 3;             // row 0..127
        int u = s & 7;              // 16B unit
        int p = mt * 128 + r;
        int n = p / IMG;
        int rem = p - n * IMG;
        int h = rem / HW;
        int w = rem - h * HW;
        hh[j] = h; ww[j] = w;
        cbase[j] = ((n * HW + h) * HW + w) * CIN + u * 8;    // in halfs
        dstA[j]  = r * 128 + ((u ^ (r & 7)) << 4);
    }
    // B: 4 slots (128 rows x 8 x 16B = 1024 uint4 / 256 thr)
    int bsrc[4];
    uint32_t dstB[4];
#pragma unroll
    for (int j = 0; j < 4; ++j) {
        int s = tid + j * 256;
        int r = s >> 3;
        int u = s & 7;
        bsrc[j] = (nt * 128 + r) * KTOT + u * 8;             // in halfs
        dstB[j] = B_OFF + r * 128 + ((u ^ (r & 7)) << 4);
    }

    // ---- warp tiling: 2 warps in M x 4 warps in N ----
    const int wm = (wid & 1) * 64;      // 0 or 64
    const int wn = (wid >> 1) * 32;     // 0,32,64,96

    float acc[4][4][4];
#pragma unroll
    for (int i = 0; i < 4; ++i)
#pragma unroll
        for (int j = 0; j < 4; ++j)
#pragma unroll
            for (int q = 0; q < 4; ++q) acc[i][j][q] = 0.f;

    auto issue_loads = [&](int it, int buf) {
        int tap = it >> 1;
        int chh = it & 1;
        int kh = tap / 3, kw = tap - kh * 3;
        const int doff = ((kh - 1) * HW + (kw - 1)) * CIN + chh * 64;  // halfs
        const uint32_t bb = smem_u + buf * BUF_BYTES;
#pragma unroll
        for (int j = 0; j < 4; ++j) {
            unsigned h2 = (unsigned)(hh[j] + kh - 1);
            unsigned w2 = (unsigned)(ww[j] + kw - 1);
            bool ok = (h2 < (unsigned)HW) && (w2 < (unsigned)HW);
            cp16(bb + dstA[j], g_xq + cbase[j] + doff, ok);
        }
        const int woff = tap * CIN + chh * 64;                          // halfs
#pragma unroll
        for (int j = 0; j < 4; ++j)
            cp16(bb + dstB[j], g_wbin + bsrc[j] + woff, true);
    };

    issue_loads(0, 0); CP_COMMIT();
    issue_loads(1, 1); CP_COMMIT();

    const int arow = wm + (lane & 15);
    const int brow = wn + (lane & 15);
    const int khi  = (lane >> 4) << 4;   // byte half select

    for (int it = 0; it < 18; ++it) {
        CP_WAIT1();                 // chunk `it` resident (<=1 group outstanding)
        __syncthreads();            // all warps past chunk it-1; its buffer free
        {
            int nx = it + 2;
            if (nx < 18) {
                int nb3 = nx % 3;
                issue_loads(nx, nb3);
            }
        }
        CP_COMMIT();

        const uint32_t bb    = smem_u + (it % 3) * BUF_BYTES;
        const uint32_t Abase = bb;
        const uint32_t Bbase = bb + B_OFF;

#pragma unroll
        for (int ks = 0; ks < 4; ++ks) {
            const int kb = ks * 32 + khi;    // byte col
            uint32_t a[4][4];
#pragma unroll
            for (int mf = 0; mf < 4; ++mf) {
                int row = arow + mf * 16;
                uint32_t off = (uint32_t)(row * 128 + kb) ^ (uint32_t)((row & 7) << 4);
                ldsm4(a[mf], Abase + off);
            }
            uint32_t b[2][4];
#pragma unroll
            for (int q = 0; q < 2; ++q) {
                int row = brow + q * 16;
                uint32_t off = (uint32_t)(row * 128 + kb) ^ (uint32_t)((row & 7) << 4);
                ldsm4(b[q], Bbase + off);
            }
#pragma unroll
            for (int mf = 0; mf < 4; ++mf)
#pragma unroll
                for (int nb = 0; nb < 4; ++nb) {
                    int q = nb >> 1, jj = nb & 1;
                    mma_f16(acc[mf][nb], a[mf], b[q][jj], b[q][jj + 2]);
                }
        }
    }

    // ---- epilogue: registers -> gmem ----
    const int r0 = lane >> 2;
    const int c0 = (lane & 3) * 2;
#pragma unroll
    for (int mf = 0; mf < 4; ++mf) {
        int m = mt * 128 + wm + mf * 16 + r0;
#pragma unroll
        for (int nb = 0; nb < 4; ++nb) {
            int co = nt * 128 + wn + nb * 8 + c0;
            float* p0 = out + (size_t)m * COUT + co;
            float* p1 = out + (size_t)(m + 8) * COUT + co;
            *(float2*)p0 = make_float2(acc[mf][nb][0], acc[mf][nb][1]);
            *(float2*)p1 = make_float2(acc[mf][nb][2], acc[mf][nb][3]);
        }
    }
}

// ---------------- launch ----------------
extern "C" void kernel_launch(void* const* d_in, const int* in_sizes, int n_in,
                              void* d_out, int out_size) {
    const float* x = (const float*)d_in[0];
    const float* w = (const float*)d_in[1];
    float* out = (float*)d_out;

    cudaFuncSetAttribute(conv_kernel,
                         cudaFuncAttributeMaxDynamicSharedMemorySize, DYN_SMEM);

    binarize_kernel<<<(COUT * KTOT + 255) / 256, 256>>>(w);
    quant_kernel<<<(NPOS * CIN / 4 + 255) / 256, 256>>>((const float4*)x);
    conv_kernel<<<NPOS / 128, 256, DYN_SMEM>>>(out, 0);
    conv_kernel<<<NPOS / 128, 256, DYN_SMEM>>>(out, 1);
}